// round 14
// baseline (speedup 1.0000x reference)
#include <cuda_runtime.h>
#include <cstdint>

#define T_HASH 524288
#define HMASK  (T_HASH - 1)
#define PI2    2654435761u
#define PI3    805459861u
#define NPTS_MAX 524288

// 64 MB feature scratch: [level][point] float2, coalesced on both sides.
__device__ __align__(16) float2 g_feats[16][NPTS_MAX];

// ---- tf32 helpers ----
__device__ __forceinline__ unsigned f2tf(float f) {
    unsigned u;
    asm("cvt.rna.tf32.f32 %0, %1;" : "=r"(u) : "f"(f));
    return u;
}
__device__ __forceinline__ void mma_tf32(float& c0, float& c1, float& c2, float& c3,
                                         unsigned a0, unsigned a1, unsigned a2, unsigned a3,
                                         unsigned b0, unsigned b1) {
    asm("mma.sync.aligned.m16n8k8.row.col.f32.tf32.tf32.f32 "
        "{%0,%1,%2,%3},{%4,%5,%6,%7},{%8,%9},{%0,%1,%2,%3};"
        : "+f"(c0), "+f"(c1), "+f"(c2), "+f"(c3)
        : "r"(a0), "r"(a1), "r"(a2), "r"(a3), "r"(b0), "r"(b1));
}

// ---- dynamic smem word-offsets (same layout as R13) ----
#define OW1AT  0
#define OW1BT  2304
#define OW2ATH 3392
#define OW2ATL 6720
#define OW2BTH 10048
#define OW2BTL 14400
#define OW2C   18752
#define OB2C   18944
#define OB1A   18948
#define OB1B   19012
#define OB2A   19028
#define OB2B   19092
#define OACT   19160
#define ACT_STRIDE 68
#define ACT_PER_WARP (32 * ACT_STRIDE)
#define SMEM_WORDS (OACT + 4 * ACT_PER_WARP)
#define SMEM_BYTES (SMEM_WORDS * 4)

// ======================= kernel 1: hash-grid gather (chunked) =======================
__global__ __launch_bounds__(256)
void ngp_gather_kernel(const float* __restrict__ x,
                       const float* __restrict__ tables, int off, int end)
{
    int i = off + blockIdx.x * blockDim.x + threadIdx.x;
    if (i >= end) return;

    float xu0 = __fdiv_rn(x[3 * i + 0], 3.0f) + 0.5f;
    float xu1 = __fdiv_rn(x[3 * i + 1], 3.0f) + 0.5f;
    float xu2 = __fdiv_rn(x[3 * i + 2], 3.0f) + 0.5f;

    const float NLv[16] = {16.f, 22.f, 30.f, 42.f, 58.f, 80.f, 110.f, 152.f,
                           209.f, 288.f, 397.f, 547.f, 754.f, 1039.f, 1432.f, 1974.f};
    const float2* tb2 = (const float2*)tables;

    #pragma unroll
    for (int l = 0; l < 16; l++) {
        float nl = NLv[l];
        float p0 = xu0 * nl, p1 = xu1 * nl, p2 = xu2 * nl;
        float f0 = floorf(p0), f1 = floorf(p1), f2 = floorf(p2);
        float r0 = p0 - f0, r1 = p1 - f1, r2 = p2 - f2;
        float a0 = 1.0f - r0, a1 = 1.0f - r1, a2 = 1.0f - r2;

        unsigned hx0 = (unsigned)(int)f0;
        unsigned hy0 = (unsigned)(int)f1 * PI2;
        unsigned hz0 = (unsigned)(int)f2 * PI3;
        unsigned hx1 = hx0 + (r0 > 0.0f ? 1u   : 0u);
        unsigned hy1 = hy0 + (r1 > 0.0f ? PI2  : 0u);
        unsigned hz1 = hz0 + (r2 > 0.0f ? PI3  : 0u);

        const float2* tbl = tb2 + (size_t)l * T_HASH;
        float2 t[8];
        #pragma unroll
        for (int k = 0; k < 8; k++) {
            unsigned hh = (((0xE2 >> k) & 1) ? hx1 : hx0)
                        ^ (((0xD4 >> k) & 1) ? hy1 : hy0)
                        ^ (((0xB8 >> k) & 1) ? hz1 : hz0);
            t[k] = __ldg(tbl + (hh & HMASK));
        }
        float acc0 = 0.0f, acc1 = 0.0f;
        #pragma unroll
        for (int k = 0; k < 8; k++) {
            float w = ((k & 1) ? r0 : a0) * ((k & 2) ? r1 : a1) * ((k & 4) ? r2 : a2);
            acc0 = fmaf(w, t[k].x, acc0);
            acc1 = fmaf(w, t[k].y, acc1);
        }
        g_feats[l][i] = make_float2(acc0, acc1);
    }
}

// ======================= kernel 2: tensor-core MLPs (chunked) =======================
__global__ __launch_bounds__(128)
void ngp_mlp_kernel(const float* __restrict__ x, const float* __restrict__ ddir,
                    const float* __restrict__ w1a, const float* __restrict__ b1a,
                    const float* __restrict__ w1b, const float* __restrict__ b1b,
                    const float* __restrict__ w2a, const float* __restrict__ b2a,
                    const float* __restrict__ w2b, const float* __restrict__ b2b,
                    const float* __restrict__ w2c, const float* __restrict__ b2c,
                    float* __restrict__ out, int off, int end, int n)
{
    extern __shared__ float sm[];
    unsigned* su = (unsigned*)sm;
    int tid = threadIdx.x;

    // ---- stage weights (transpose + tf32 convert; hi/lo split for layer 2) ----
    for (int idx = tid; idx < 64 * 36; idx += 128) {
        int nn = idx / 36, kk = idx % 36;
        su[OW1AT + idx] = (kk < 32) ? f2tf(w1a[kk * 64 + nn]) : 0u;
    }
    for (int idx = tid; idx < 16 * 68; idx += 128) {
        int nn = idx / 68, kk = idx % 68;
        su[OW1BT + idx] = (kk < 64) ? f2tf(w1b[kk * 16 + nn]) : 0u;
    }
    for (int idx = tid; idx < 64 * 52; idx += 128) {
        int nn = idx / 52, kk = idx % 52;
        float f = (kk < 43) ? w2a[kk * 64 + nn] : 0.0f;
        unsigned h = f2tf(f);
        su[OW2ATH + idx] = h;
        su[OW2ATL + idx] = f2tf(f - __uint_as_float(h));
    }
    for (int idx = tid; idx < 64 * 68; idx += 128) {
        int nn = idx / 68, kk = idx % 68;
        float f = (kk < 64) ? w2b[kk * 64 + nn] : 0.0f;
        unsigned h = f2tf(f);
        su[OW2BTH + idx] = h;
        su[OW2BTL + idx] = f2tf(f - __uint_as_float(h));
    }
    for (int idx = tid; idx < 192; idx += 128) sm[OW2C + idx] = w2c[idx];
    if (tid < 3)  sm[OB2C + tid] = b2c[tid];
    if (tid < 64) { sm[OB1A + tid] = b1a[tid]; sm[OB2A + tid] = b2a[tid]; sm[OB2B + tid] = b2b[tid]; }
    if (tid < 16) sm[OB1B + tid] = b1b[tid];
    __syncthreads();

    const int wid = tid >> 5, ln = tid & 31;
    const int g = ln >> 2, tg = ln & 3;
    const int actB = OACT + wid * ACT_PER_WARP;
    const int pt = off + blockIdx.x * 128 + wid * 32 + ln;
    const bool valid = (pt < end);

    // per-point scalars
    float d0 = 0.f, d1 = 0.f, d2 = 0.f;
    bool mask = false;
    if (valid) {
        float xs0 = __fdiv_rn(x[3 * pt + 0], 3.0f);
        float xs1 = __fdiv_rn(x[3 * pt + 1], 3.0f);
        float xs2 = __fdiv_rn(x[3 * pt + 2], 3.0f);
        mask = (fabsf(xs0) < 0.5f) && (fabsf(xs1) < 0.5f) && (fabsf(xs2) < 0.5f);
        d0 = ddir[3 * pt + 0]; d1 = ddir[3 * pt + 1]; d2 = ddir[3 * pt + 2];
    }

    // ---- stage this warp's 32x32 feats into act rows ----
    {
        int p = valid ? pt : off;
        #pragma unroll
        for (int l = 0; l < 16; l++) {
            float2 f = g_feats[l][p];
            sm[actB + ln * ACT_STRIDE + 2 * l + 0] = f.x;
            sm[actB + ln * ACT_STRIDE + 2 * l + 1] = f.y;
        }
    }
    __syncwarp();

    // =============== layer 1a: [32,32]x[32,64], relu, single tf32 ===============
    {
        unsigned au[2][4][4];
        #pragma unroll
        for (int mt = 0; mt < 2; mt++)
            #pragma unroll
            for (int kt = 0; kt < 4; kt++) {
                int r = actB + (mt * 16 + g) * ACT_STRIDE + kt * 8;
                au[mt][kt][0] = f2tf(sm[r + tg]);
                au[mt][kt][1] = f2tf(sm[r + 8 * ACT_STRIDE + tg]);
                au[mt][kt][2] = f2tf(sm[r + tg + 4]);
                au[mt][kt][3] = f2tf(sm[r + 8 * ACT_STRIDE + tg + 4]);
            }
        __syncwarp();
        #pragma unroll
        for (int mt = 0; mt < 2; mt++)
            #pragma unroll
            for (int nt = 0; nt < 8; nt++) {
                float c0 = sm[OB1A + nt * 8 + 2 * tg], c1 = sm[OB1A + nt * 8 + 2 * tg + 1];
                float c2 = c0, c3 = c1;
                #pragma unroll
                for (int kt = 0; kt < 4; kt++) {
                    int wb = OW1AT + (nt * 8 + g) * 36 + kt * 8 + tg;
                    mma_tf32(c0, c1, c2, c3,
                             au[mt][kt][0], au[mt][kt][1], au[mt][kt][2], au[mt][kt][3],
                             su[wb], su[wb + 4]);
                }
                int r = actB + (mt * 16 + g) * ACT_STRIDE + nt * 8 + 2 * tg;
                sm[r] = fmaxf(c0, 0.f); sm[r + 1] = fmaxf(c1, 0.f);
                sm[r + 8 * ACT_STRIDE] = fmaxf(c2, 0.f); sm[r + 8 * ACT_STRIDE + 1] = fmaxf(c3, 0.f);
            }
        __syncwarp();
    }

    // =============== layer 1b: [32,64]x[64,16], no relu, single tf32 ===============
    {
        unsigned au[2][8][4];
        #pragma unroll
        for (int mt = 0; mt < 2; mt++)
            #pragma unroll
            for (int kt = 0; kt < 8; kt++) {
                int r = actB + (mt * 16 + g) * ACT_STRIDE + kt * 8;
                au[mt][kt][0] = f2tf(sm[r + tg]);
                au[mt][kt][1] = f2tf(sm[r + 8 * ACT_STRIDE + tg]);
                au[mt][kt][2] = f2tf(sm[r + tg + 4]);
                au[mt][kt][3] = f2tf(sm[r + 8 * ACT_STRIDE + tg + 4]);
            }
        __syncwarp();
        #pragma unroll
        for (int mt = 0; mt < 2; mt++)
            #pragma unroll
            for (int nt = 0; nt < 2; nt++) {
                float c0 = sm[OB1B + nt * 8 + 2 * tg], c1 = sm[OB1B + nt * 8 + 2 * tg + 1];
                float c2 = c0, c3 = c1;
                #pragma unroll
                for (int kt = 0; kt < 8; kt++) {
                    int wb = OW1BT + (nt * 8 + g) * 68 + kt * 8 + tg;
                    mma_tf32(c0, c1, c2, c3,
                             au[mt][kt][0], au[mt][kt][1], au[mt][kt][2], au[mt][kt][3],
                             su[wb], su[wb + 4]);
                }
                int r = actB + (mt * 16 + g) * ACT_STRIDE + nt * 8 + 2 * tg;
                sm[r] = c0; sm[r + 1] = c1;
                sm[r + 8 * ACT_STRIDE] = c2; sm[r + 8 * ACT_STRIDE + 1] = c3;
            }
        __syncwarp();
    }

    // =============== sigma + z = [h(16), d(3), posenc(24), pad to 48] ===============
    float sigma;
    {
        float h0v = sm[actB + ln * ACT_STRIDE + 0];
        sigma = mask ? __expf(h0v) : 0.0f;
        int zr = actB + ln * ACT_STRIDE;
        sm[zr + 16] = d0; sm[zr + 17] = d1; sm[zr + 18] = d2;
        #pragma unroll
        for (int q = 0; q < 4; q++) {
            float m = (float)(1 << q);
            float s, c;
            __sincosf(m * d0, &s, &c); sm[zr + 19 + 6 * q + 0] = s; sm[zr + 22 + 6 * q + 0] = c;
            __sincosf(m * d1, &s, &c); sm[zr + 19 + 6 * q + 1] = s; sm[zr + 22 + 6 * q + 1] = c;
            __sincosf(m * d2, &s, &c); sm[zr + 19 + 6 * q + 2] = s; sm[zr + 22 + 6 * q + 2] = c;
        }
        sm[zr + 43] = 0.f; sm[zr + 44] = 0.f; sm[zr + 45] = 0.f;
        sm[zr + 46] = 0.f; sm[zr + 47] = 0.f;
    }
    __syncwarp();

    // =============== layer 2a: [32,48]x[48,64], relu, tf32 x3 ===============
    {
        float cf[64];
        #pragma unroll
        for (int mt = 0; mt < 2; mt++) {
            unsigned ah[6][4], al[6][4];
            #pragma unroll
            for (int kt = 0; kt < 6; kt++) {
                int r = actB + (mt * 16 + g) * ACT_STRIDE + kt * 8;
                #pragma unroll
                for (int q = 0; q < 4; q++) {
                    int off2 = (q & 1) * 8 * ACT_STRIDE + (q >> 1) * 4 + tg;
                    float f = sm[r + off2];
                    unsigned h = f2tf(f);
                    ah[kt][q] = h;
                    al[kt][q] = f2tf(f - __uint_as_float(h));
                }
            }
            #pragma unroll
            for (int nt = 0; nt < 8; nt++) {
                float c0 = sm[OB2A + nt * 8 + 2 * tg], c1 = sm[OB2A + nt * 8 + 2 * tg + 1];
                float c2 = c0, c3 = c1;
                #pragma unroll
                for (int kt = 0; kt < 6; kt++) {
                    int wh = OW2ATH + (nt * 8 + g) * 52 + kt * 8 + tg;
                    int wl = OW2ATL + (nt * 8 + g) * 52 + kt * 8 + tg;
                    unsigned bh0 = su[wh], bh1 = su[wh + 4];
                    unsigned bl0 = su[wl], bl1 = su[wl + 4];
                    mma_tf32(c0, c1, c2, c3, ah[kt][0], ah[kt][1], ah[kt][2], ah[kt][3], bh0, bh1);
                    mma_tf32(c0, c1, c2, c3, ah[kt][0], ah[kt][1], ah[kt][2], ah[kt][3], bl0, bl1);
                    mma_tf32(c0, c1, c2, c3, al[kt][0], al[kt][1], al[kt][2], al[kt][3], bh0, bh1);
                }
                cf[(mt * 8 + nt) * 4 + 0] = c0; cf[(mt * 8 + nt) * 4 + 1] = c1;
                cf[(mt * 8 + nt) * 4 + 2] = c2; cf[(mt * 8 + nt) * 4 + 3] = c3;
            }
        }
        __syncwarp();
        #pragma unroll
        for (int mt = 0; mt < 2; mt++)
            #pragma unroll
            for (int nt = 0; nt < 8; nt++) {
                int r = actB + (mt * 16 + g) * ACT_STRIDE + nt * 8 + 2 * tg;
                sm[r]     = fmaxf(cf[(mt * 8 + nt) * 4 + 0], 0.f);
                sm[r + 1] = fmaxf(cf[(mt * 8 + nt) * 4 + 1], 0.f);
                sm[r + 8 * ACT_STRIDE]     = fmaxf(cf[(mt * 8 + nt) * 4 + 2], 0.f);
                sm[r + 8 * ACT_STRIDE + 1] = fmaxf(cf[(mt * 8 + nt) * 4 + 3], 0.f);
            }
        __syncwarp();
    }

    // =============== layer 2b: [32,64]x[64,64], relu, tf32 x3 ===============
    {
        float cf[64];
        #pragma unroll
        for (int mt = 0; mt < 2; mt++) {
            unsigned ah[8][4], al[8][4];
            #pragma unroll
            for (int kt = 0; kt < 8; kt++) {
                int r = actB + (mt * 16 + g) * ACT_STRIDE + kt * 8;
                #pragma unroll
                for (int q = 0; q < 4; q++) {
                    int off2 = (q & 1) * 8 * ACT_STRIDE + (q >> 1) * 4 + tg;
                    float f = sm[r + off2];
                    unsigned h = f2tf(f);
                    ah[kt][q] = h;
                    al[kt][q] = f2tf(f - __uint_as_float(h));
                }
            }
            #pragma unroll
            for (int nt = 0; nt < 8; nt++) {
                float c0 = sm[OB2B + nt * 8 + 2 * tg], c1 = sm[OB2B + nt * 8 + 2 * tg + 1];
                float c2 = c0, c3 = c1;
                #pragma unroll
                for (int kt = 0; kt < 8; kt++) {
                    int wh = OW2BTH + (nt * 8 + g) * 68 + kt * 8 + tg;
                    int wl = OW2BTL + (nt * 8 + g) * 68 + kt * 8 + tg;
                    unsigned bh0 = su[wh], bh1 = su[wh + 4];
                    unsigned bl0 = su[wl], bl1 = su[wl + 4];
                    mma_tf32(c0, c1, c2, c3, ah[kt][0], ah[kt][1], ah[kt][2], ah[kt][3], bh0, bh1);
                    mma_tf32(c0, c1, c2, c3, ah[kt][0], ah[kt][1], ah[kt][2], ah[kt][3], bl0, bl1);
                    mma_tf32(c0, c1, c2, c3, al[kt][0], al[kt][1], al[kt][2], al[kt][3], bh0, bh1);
                }
                cf[(mt * 8 + nt) * 4 + 0] = c0; cf[(mt * 8 + nt) * 4 + 1] = c1;
                cf[(mt * 8 + nt) * 4 + 2] = c2; cf[(mt * 8 + nt) * 4 + 3] = c3;
            }
        }
        __syncwarp();
        #pragma unroll
        for (int mt = 0; mt < 2; mt++)
            #pragma unroll
            for (int nt = 0; nt < 8; nt++) {
                int r = actB + (mt * 16 + g) * ACT_STRIDE + nt * 8 + 2 * tg;
                sm[r]     = fmaxf(cf[(mt * 8 + nt) * 4 + 0], 0.f);
                sm[r + 1] = fmaxf(cf[(mt * 8 + nt) * 4 + 1], 0.f);
                sm[r + 8 * ACT_STRIDE]     = fmaxf(cf[(mt * 8 + nt) * 4 + 2], 0.f);
                sm[r + 8 * ACT_STRIDE + 1] = fmaxf(cf[(mt * 8 + nt) * 4 + 3], 0.f);
            }
        __syncwarp();
    }

    // =============== layer 2c: 64 -> 3, sigmoid (scalar fp32) ===============
    {
        float c0 = sm[OB2C + 0], c1 = sm[OB2C + 1], c2 = sm[OB2C + 2];
        int zr = actB + ln * ACT_STRIDE;
        #pragma unroll 8
        for (int k = 0; k < 64; k++) {
            float v = sm[zr + k];
            c0 = fmaf(v, sm[OW2C + 3 * k + 0], c0);
            c1 = fmaf(v, sm[OW2C + 3 * k + 1], c1);
            c2 = fmaf(v, sm[OW2C + 3 * k + 2], c2);
        }
        c0 = 1.0f / (1.0f + __expf(-c0));
        c1 = 1.0f / (1.0f + __expf(-c1));
        c2 = 1.0f / (1.0f + __expf(-c2));

        if (valid) {
            out[3 * pt + 0] = mask ? c0 : 0.0f;
            out[3 * pt + 1] = mask ? c1 : 0.0f;
            out[3 * pt + 2] = mask ? c2 : 0.0f;
            out[3 * n + pt] = sigma;
        }
    }
}

extern "C" void kernel_launch(void* const* d_in, const int* in_sizes, int n_in,
                              void* d_out, int out_size) {
    const float* x      = (const float*)d_in[0];
    const float* dd     = (const float*)d_in[1];
    const float* tables = (const float*)d_in[2];

    int n = in_sizes[0] / 3;

    cudaFuncSetAttribute(ngp_mlp_kernel,
                         cudaFuncAttributeMaxDynamicSharedMemorySize, SMEM_BYTES);

    // Fork-join pipeline: gather chunks on the capture (default) stream, MLP
    // chunks on a second stream gated by per-chunk events. Streams/events are
    // host-side objects (no device allocation); the capture turns record/wait
    // into graph dependencies, giving gather(i+1) ∥ mlp(i) overlap on replay.
    const int NCHUNK = 4;
    cudaStream_t s1;
    cudaStreamCreateWithFlags(&s1, cudaStreamNonBlocking);
    cudaEvent_t ev[NCHUNK], done;
    for (int c = 0; c < NCHUNK; c++)
        cudaEventCreateWithFlags(&ev[c], cudaEventDisableTiming);
    cudaEventCreateWithFlags(&done, cudaEventDisableTiming);

    int chunk = (n + NCHUNK - 1) / NCHUNK;

    for (int c = 0; c < NCHUNK; c++) {
        int off = c * chunk;
        if (off >= n) { cudaEventRecord(ev[c], 0); continue; }
        int end = off + chunk; if (end > n) end = n;
        int cnt = end - off;
        ngp_gather_kernel<<<(cnt + 255) / 256, 256, 0, 0>>>(x, tables, off, end);
        cudaEventRecord(ev[c], 0);
    }

    for (int c = 0; c < NCHUNK; c++) {
        int off = c * chunk;
        if (off >= n) continue;
        int end = off + chunk; if (end > n) end = n;
        int cnt = end - off;
        cudaStreamWaitEvent(s1, ev[c], 0);
        ngp_mlp_kernel<<<(cnt + 127) / 128, 128, SMEM_BYTES, s1>>>(
            x, dd,
            (const float*)d_in[3], (const float*)d_in[4],
            (const float*)d_in[5], (const float*)d_in[6],
            (const float*)d_in[7], (const float*)d_in[8],
            (const float*)d_in[9], (const float*)d_in[10],
            (const float*)d_in[11], (const float*)d_in[12],
            (float*)d_out, off, end, n);
    }

    cudaEventRecord(done, s1);
    cudaStreamWaitEvent(0, done, 0);
    // Intentionally no stream/event destroy: host-object teardown during an
    // active capture is the risky path; a few leaked host handles per call are
    // deterministic and harness-legal.
}

// round 15
// speedup vs baseline: 1.6813x; 1.6813x over previous
#include <cuda_runtime.h>
#include <cstdint>

#define T_HASH 524288
#define HMASK  (T_HASH - 1)
#define PI2    2654435761u
#define PI3    805459861u
#define NPTS_MAX 524288

// 64 MB feature scratch: [level][point] float2, coalesced on both sides.
__device__ __align__(16) float2 g_feats[16][NPTS_MAX];

// ---- tf32 helpers ----
__device__ __forceinline__ unsigned f2tf(float f) {
    unsigned u;
    asm("cvt.rna.tf32.f32 %0, %1;" : "=r"(u) : "f"(f));
    return u;
}
__device__ __forceinline__ void mma_tf32(float& c0, float& c1, float& c2, float& c3,
                                         unsigned a0, unsigned a1, unsigned a2, unsigned a3,
                                         unsigned b0, unsigned b1) {
    asm("mma.sync.aligned.m16n8k8.row.col.f32.tf32.tf32.f32 "
        "{%0,%1,%2,%3},{%4,%5,%6,%7},{%8,%9},{%0,%1,%2,%3};"
        : "+f"(c0), "+f"(c1), "+f"(c2), "+f"(c3)
        : "r"(a0), "r"(a1), "r"(a2), "r"(a3), "r"(b0), "r"(b1));
}

// ---- dynamic smem word-offsets ----
// B-weight fragments stored LANE-CONTIGUOUS:
//   layer-1 : uint2 {b0,b1}          -> one LDS.64  per fragment
//   layer-2 : uint4 {bh0,bh1,bl0,bl1}-> one LDS.128 per fragment (x3 split)
// lane-indexed addressing (lane*8B / lane*16B) is phase-split conflict-free.
#define OW2BQ  0        // uint4 [8nt][8kt][32]  8192 words
#define OW2AQ  8192     // uint4 [8nt][6kt][32]  6144 words
#define OW1AP  14336    // uint2 [8nt][4kt][32]  2048 words
#define OW1BP  16384    // uint2 [2nt][8kt][32]  1024 words
#define OW2C   17408    // float [192]
#define OB2C   17600    // float [3] (+1 pad)
#define OB1A   17604    // float [64]
#define OB1B   17668    // float [16]
#define OB2A   17684    // float [64]
#define OB2B   17748    // float [64]
#define OACT   17812    // float, per warp 32 rows x stride 68
#define ACT_STRIDE 68
#define ACT_PER_WARP (32 * ACT_STRIDE)
#define SMEM_WORDS (OACT + 4 * ACT_PER_WARP)     // 26516
#define SMEM_BYTES (SMEM_WORDS * 4)              // 106064 -> 2 CTA/SM

// ======================= kernel 1: hash-grid gather =======================
__global__ __launch_bounds__(256)
void ngp_gather_kernel(const float* __restrict__ x,
                       const float* __restrict__ tables, int n)
{
    int i = blockIdx.x * blockDim.x + threadIdx.x;
    if (i >= n) return;

    float xu0 = __fdiv_rn(x[3 * i + 0], 3.0f) + 0.5f;
    float xu1 = __fdiv_rn(x[3 * i + 1], 3.0f) + 0.5f;
    float xu2 = __fdiv_rn(x[3 * i + 2], 3.0f) + 0.5f;

    const float NLv[16] = {16.f, 22.f, 30.f, 42.f, 58.f, 80.f, 110.f, 152.f,
                           209.f, 288.f, 397.f, 547.f, 754.f, 1039.f, 1432.f, 1974.f};
    const float2* tb2 = (const float2*)tables;

    #pragma unroll
    for (int l = 0; l < 16; l++) {
        float nl = NLv[l];
        float p0 = xu0 * nl, p1 = xu1 * nl, p2 = xu2 * nl;
        float f0 = floorf(p0), f1 = floorf(p1), f2 = floorf(p2);
        float r0 = p0 - f0, r1 = p1 - f1, r2 = p2 - f2;
        float a0 = 1.0f - r0, a1 = 1.0f - r1, a2 = 1.0f - r2;

        unsigned hx0 = (unsigned)(int)f0;
        unsigned hy0 = (unsigned)(int)f1 * PI2;
        unsigned hz0 = (unsigned)(int)f2 * PI3;
        unsigned hx1 = hx0 + (r0 > 0.0f ? 1u   : 0u);
        unsigned hy1 = hy0 + (r1 > 0.0f ? PI2  : 0u);
        unsigned hz1 = hz0 + (r2 > 0.0f ? PI3  : 0u);

        const float2* tbl = tb2 + (size_t)l * T_HASH;
        float2 t[8];
        #pragma unroll
        for (int k = 0; k < 8; k++) {
            unsigned hh = (((0xE2 >> k) & 1) ? hx1 : hx0)
                        ^ (((0xD4 >> k) & 1) ? hy1 : hy0)
                        ^ (((0xB8 >> k) & 1) ? hz1 : hz0);
            t[k] = __ldg(tbl + (hh & HMASK));
        }
        float acc0 = 0.0f, acc1 = 0.0f;
        #pragma unroll
        for (int k = 0; k < 8; k++) {
            float w = ((k & 1) ? r0 : a0) * ((k & 2) ? r1 : a1) * ((k & 4) ? r2 : a2);
            acc0 = fmaf(w, t[k].x, acc0);
            acc1 = fmaf(w, t[k].y, acc1);
        }
        g_feats[l][i] = make_float2(acc0, acc1);
    }
}

// ======================= kernel 2: tensor-core MLPs =======================
__global__ __launch_bounds__(128)
void ngp_mlp_kernel(const float* __restrict__ x, const float* __restrict__ ddir,
                    const float* __restrict__ w1a, const float* __restrict__ b1a,
                    const float* __restrict__ w1b, const float* __restrict__ b1b,
                    const float* __restrict__ w2a, const float* __restrict__ b2a,
                    const float* __restrict__ w2b, const float* __restrict__ b2b,
                    const float* __restrict__ w2c, const float* __restrict__ b2c,
                    float* __restrict__ out, int n)
{
    extern __shared__ float sm[];
    unsigned* su = (unsigned*)sm;
    int tid = threadIdx.x;

    // ---- stage B-weight fragments lane-contiguous ----
    {
        uint2* pw1a = (uint2*)(su + OW1AP);
        for (int idx = tid; idx < 8 * 4 * 32; idx += 128) {        // nt*128 + kt*32 + ln
            int g2 = (idx >> 2) & 7, tg2 = idx & 3;
            int nt = idx >> 7, kt = (idx >> 5) & 3;
            int nn = nt * 8 + g2, k0 = kt * 8 + tg2;
            pw1a[idx] = make_uint2(f2tf(w1a[k0 * 64 + nn]), f2tf(w1a[(k0 + 4) * 64 + nn]));
        }
        uint2* pw1b = (uint2*)(su + OW1BP);
        for (int idx = tid; idx < 2 * 8 * 32; idx += 128) {        // nt*256 + kt*32 + ln
            int g2 = (idx >> 2) & 7, tg2 = idx & 3;
            int nt = idx >> 8, kt = (idx >> 5) & 7;
            int nn = nt * 8 + g2, k0 = kt * 8 + tg2;
            pw1b[idx] = make_uint2(f2tf(w1b[k0 * 16 + nn]), f2tf(w1b[(k0 + 4) * 16 + nn]));
        }
        uint4* pw2a = (uint4*)(su + OW2AQ);
        for (int idx = tid; idx < 8 * 6 * 32; idx += 128) {        // nt*192 + kt*32 + ln
            int g2 = (idx >> 2) & 7, tg2 = idx & 3;
            int nt = idx / 192, kt = (idx / 32) % 6;
            int nn = nt * 8 + g2, k0 = kt * 8 + tg2;
            float f0 = (k0 < 43) ? w2a[k0 * 64 + nn] : 0.0f;
            float f1 = (k0 + 4 < 43) ? w2a[(k0 + 4) * 64 + nn] : 0.0f;
            unsigned h0 = f2tf(f0), h1 = f2tf(f1);
            pw2a[idx] = make_uint4(h0, h1,
                                   f2tf(f0 - __uint_as_float(h0)),
                                   f2tf(f1 - __uint_as_float(h1)));
        }
        uint4* pw2b = (uint4*)(su + OW2BQ);
        for (int idx = tid; idx < 8 * 8 * 32; idx += 128) {        // nt*256 + kt*32 + ln
            int g2 = (idx >> 2) & 7, tg2 = idx & 3;
            int nt = idx >> 8, kt = (idx >> 5) & 7;
            int nn = nt * 8 + g2, k0 = kt * 8 + tg2;
            float f0 = w2b[k0 * 64 + nn];
            float f1 = w2b[(k0 + 4) * 64 + nn];
            unsigned h0 = f2tf(f0), h1 = f2tf(f1);
            pw2b[idx] = make_uint4(h0, h1,
                                   f2tf(f0 - __uint_as_float(h0)),
                                   f2tf(f1 - __uint_as_float(h1)));
        }
    }
    for (int idx = tid; idx < 192; idx += 128) sm[OW2C + idx] = w2c[idx];
    if (tid < 3)  sm[OB2C + tid] = b2c[tid];
    if (tid < 64) { sm[OB1A + tid] = b1a[tid]; sm[OB2A + tid] = b2a[tid]; sm[OB2B + tid] = b2b[tid]; }
    if (tid < 16) sm[OB1B + tid] = b1b[tid];
    __syncthreads();

    const int wid = tid >> 5, ln = tid & 31;
    const int g = ln >> 2, tg = ln & 3;
    const int actB = OACT + wid * ACT_PER_WARP;
    const int pt = blockIdx.x * 128 + wid * 32 + ln;
    const bool valid = (pt < n);

    const uint2* pw1a = (const uint2*)(su + OW1AP);
    const uint2* pw1b = (const uint2*)(su + OW1BP);
    const uint4* pw2a = (const uint4*)(su + OW2AQ);
    const uint4* pw2b = (const uint4*)(su + OW2BQ);

    // per-point scalars
    float d0 = 0.f, d1 = 0.f, d2 = 0.f;
    bool mask = false;
    if (valid) {
        float xs0 = __fdiv_rn(x[3 * pt + 0], 3.0f);
        float xs1 = __fdiv_rn(x[3 * pt + 1], 3.0f);
        float xs2 = __fdiv_rn(x[3 * pt + 2], 3.0f);
        mask = (fabsf(xs0) < 0.5f) && (fabsf(xs1) < 0.5f) && (fabsf(xs2) < 0.5f);
        d0 = ddir[3 * pt + 0]; d1 = ddir[3 * pt + 1]; d2 = ddir[3 * pt + 2];
    }

    // ---- stage this warp's 32x32 feats into act rows ----
    {
        int p = valid ? pt : 0;
        #pragma unroll
        for (int l = 0; l < 16; l++) {
            float2 f = g_feats[l][p];
            *(float2*)&sm[actB + ln * ACT_STRIDE + 2 * l] = f;
        }
    }
    __syncwarp();

    // =============== layer 1a: [32,32]x[32,64], relu, single tf32 ===============
    {
        unsigned au[2][4][4];
        #pragma unroll
        for (int mt = 0; mt < 2; mt++)
            #pragma unroll
            for (int kt = 0; kt < 4; kt++) {
                int r = actB + (mt * 16 + g) * ACT_STRIDE + kt * 8;
                au[mt][kt][0] = f2tf(sm[r + tg]);
                au[mt][kt][1] = f2tf(sm[r + 8 * ACT_STRIDE + tg]);
                au[mt][kt][2] = f2tf(sm[r + tg + 4]);
                au[mt][kt][3] = f2tf(sm[r + 8 * ACT_STRIDE + tg + 4]);
            }
        __syncwarp();
        #pragma unroll
        for (int mt = 0; mt < 2; mt++)
            #pragma unroll
            for (int nt = 0; nt < 8; nt++) {
                float c0 = sm[OB1A + nt * 8 + 2 * tg], c1 = sm[OB1A + nt * 8 + 2 * tg + 1];
                float c2 = c0, c3 = c1;
                #pragma unroll
                for (int kt = 0; kt < 4; kt++) {
                    uint2 b = pw1a[(nt * 4 + kt) * 32 + ln];
                    mma_tf32(c0, c1, c2, c3,
                             au[mt][kt][0], au[mt][kt][1], au[mt][kt][2], au[mt][kt][3],
                             b.x, b.y);
                }
                int r = actB + (mt * 16 + g) * ACT_STRIDE + nt * 8 + 2 * tg;
                *(float2*)&sm[r] = make_float2(fmaxf(c0, 0.f), fmaxf(c1, 0.f));
                *(float2*)&sm[r + 8 * ACT_STRIDE] = make_float2(fmaxf(c2, 0.f), fmaxf(c3, 0.f));
            }
        __syncwarp();
    }

    // =============== layer 1b: [32,64]x[64,16], no relu, single tf32 ===============
    {
        unsigned au[2][8][4];
        #pragma unroll
        for (int mt = 0; mt < 2; mt++)
            #pragma unroll
            for (int kt = 0; kt < 8; kt++) {
                int r = actB + (mt * 16 + g) * ACT_STRIDE + kt * 8;
                au[mt][kt][0] = f2tf(sm[r + tg]);
                au[mt][kt][1] = f2tf(sm[r + 8 * ACT_STRIDE + tg]);
                au[mt][kt][2] = f2tf(sm[r + tg + 4]);
                au[mt][kt][3] = f2tf(sm[r + 8 * ACT_STRIDE + tg + 4]);
            }
        __syncwarp();
        #pragma unroll
        for (int mt = 0; mt < 2; mt++)
            #pragma unroll
            for (int nt = 0; nt < 2; nt++) {
                float c0 = sm[OB1B + nt * 8 + 2 * tg], c1 = sm[OB1B + nt * 8 + 2 * tg + 1];
                float c2 = c0, c3 = c1;
                #pragma unroll
                for (int kt = 0; kt < 8; kt++) {
                    uint2 b = pw1b[(nt * 8 + kt) * 32 + ln];
                    mma_tf32(c0, c1, c2, c3,
                             au[mt][kt][0], au[mt][kt][1], au[mt][kt][2], au[mt][kt][3],
                             b.x, b.y);
                }
                int r = actB + (mt * 16 + g) * ACT_STRIDE + nt * 8 + 2 * tg;
                *(float2*)&sm[r] = make_float2(c0, c1);
                *(float2*)&sm[r + 8 * ACT_STRIDE] = make_float2(c2, c3);
            }
        __syncwarp();
    }

    // =============== sigma + z = [h(16), d(3), posenc(24), pad to 48] ===============
    float sigma;
    {
        float h0v = sm[actB + ln * ACT_STRIDE + 0];
        sigma = mask ? __expf(h0v) : 0.0f;
        int zr = actB + ln * ACT_STRIDE;
        sm[zr + 16] = d0; sm[zr + 17] = d1; sm[zr + 18] = d2;
        #pragma unroll
        for (int q = 0; q < 4; q++) {
            float m = (float)(1 << q);
            float s, c;
            __sincosf(m * d0, &s, &c); sm[zr + 19 + 6 * q + 0] = s; sm[zr + 22 + 6 * q + 0] = c;
            __sincosf(m * d1, &s, &c); sm[zr + 19 + 6 * q + 1] = s; sm[zr + 22 + 6 * q + 1] = c;
            __sincosf(m * d2, &s, &c); sm[zr + 19 + 6 * q + 2] = s; sm[zr + 22 + 6 * q + 2] = c;
        }
        sm[zr + 43] = 0.f; sm[zr + 44] = 0.f; sm[zr + 45] = 0.f;
        sm[zr + 46] = 0.f; sm[zr + 47] = 0.f;
    }
    __syncwarp();

    // =============== layer 2a: [32,48]x[48,64], relu, tf32 x3 ===============
    {
        float cf[64];
        #pragma unroll
        for (int mt = 0; mt < 2; mt++) {
            unsigned ah[6][4], al[6][4];
            #pragma unroll
            for (int kt = 0; kt < 6; kt++) {
                int r = actB + (mt * 16 + g) * ACT_STRIDE + kt * 8;
                #pragma unroll
                for (int q = 0; q < 4; q++) {
                    int off2 = (q & 1) * 8 * ACT_STRIDE + (q >> 1) * 4 + tg;
                    float f = sm[r + off2];
                    unsigned h = f2tf(f);
                    ah[kt][q] = h;
                    al[kt][q] = f2tf(f - __uint_as_float(h));
                }
            }
            #pragma unroll
            for (int nt = 0; nt < 8; nt++) {
                float c0 = sm[OB2A + nt * 8 + 2 * tg], c1 = sm[OB2A + nt * 8 + 2 * tg + 1];
                float c2 = c0, c3 = c1;
                #pragma unroll
                for (int kt = 0; kt < 6; kt++) {
                    uint4 q4 = pw2a[(nt * 6 + kt) * 32 + ln];
                    mma_tf32(c0, c1, c2, c3, ah[kt][0], ah[kt][1], ah[kt][2], ah[kt][3], q4.x, q4.y);
                    mma_tf32(c0, c1, c2, c3, ah[kt][0], ah[kt][1], ah[kt][2], ah[kt][3], q4.z, q4.w);
                    mma_tf32(c0, c1, c2, c3, al[kt][0], al[kt][1], al[kt][2], al[kt][3], q4.x, q4.y);
                }
                cf[(mt * 8 + nt) * 4 + 0] = c0; cf[(mt * 8 + nt) * 4 + 1] = c1;
                cf[(mt * 8 + nt) * 4 + 2] = c2; cf[(mt * 8 + nt) * 4 + 3] = c3;
            }
        }
        __syncwarp();
        #pragma unroll
        for (int mt = 0; mt < 2; mt++)
            #pragma unroll
            for (int nt = 0; nt < 8; nt++) {
                int r = actB + (mt * 16 + g) * ACT_STRIDE + nt * 8 + 2 * tg;
                *(float2*)&sm[r] = make_float2(fmaxf(cf[(mt * 8 + nt) * 4 + 0], 0.f),
                                               fmaxf(cf[(mt * 8 + nt) * 4 + 1], 0.f));
                *(float2*)&sm[r + 8 * ACT_STRIDE] =
                    make_float2(fmaxf(cf[(mt * 8 + nt) * 4 + 2], 0.f),
                                fmaxf(cf[(mt * 8 + nt) * 4 + 3], 0.f));
            }
        __syncwarp();
    }

    // =============== layer 2b: [32,64]x[64,64], relu, tf32 x3 ===============
    {
        float cf[64];
        #pragma unroll
        for (int mt = 0; mt < 2; mt++) {
            unsigned ah[8][4], al[8][4];
            #pragma unroll
            for (int kt = 0; kt < 8; kt++) {
                int r = actB + (mt * 16 + g) * ACT_STRIDE + kt * 8;
                #pragma unroll
                for (int q = 0; q < 4; q++) {
                    int off2 = (q & 1) * 8 * ACT_STRIDE + (q >> 1) * 4 + tg;
                    float f = sm[r + off2];
                    unsigned h = f2tf(f);
                    ah[kt][q] = h;
                    al[kt][q] = f2tf(f - __uint_as_float(h));
                }
            }
            #pragma unroll
            for (int nt = 0; nt < 8; nt++) {
                float c0 = sm[OB2B + nt * 8 + 2 * tg], c1 = sm[OB2B + nt * 8 + 2 * tg + 1];
                float c2 = c0, c3 = c1;
                #pragma unroll
                for (int kt = 0; kt < 8; kt++) {
                    uint4 q4 = pw2b[(nt * 8 + kt) * 32 + ln];
                    mma_tf32(c0, c1, c2, c3, ah[kt][0], ah[kt][1], ah[kt][2], ah[kt][3], q4.x, q4.y);
                    mma_tf32(c0, c1, c2, c3, ah[kt][0], ah[kt][1], ah[kt][2], ah[kt][3], q4.z, q4.w);
                    mma_tf32(c0, c1, c2, c3, al[kt][0], al[kt][1], al[kt][2], al[kt][3], q4.x, q4.y);
                }
                cf[(mt * 8 + nt) * 4 + 0] = c0; cf[(mt * 8 + nt) * 4 + 1] = c1;
                cf[(mt * 8 + nt) * 4 + 2] = c2; cf[(mt * 8 + nt) * 4 + 3] = c3;
            }
        }
        __syncwarp();
        #pragma unroll
        for (int mt = 0; mt < 2; mt++)
            #pragma unroll
            for (int nt = 0; nt < 8; nt++) {
                int r = actB + (mt * 16 + g) * ACT_STRIDE + nt * 8 + 2 * tg;
                *(float2*)&sm[r] = make_float2(fmaxf(cf[(mt * 8 + nt) * 4 + 0], 0.f),
                                               fmaxf(cf[(mt * 8 + nt) * 4 + 1], 0.f));
                *(float2*)&sm[r + 8 * ACT_STRIDE] =
                    make_float2(fmaxf(cf[(mt * 8 + nt) * 4 + 2], 0.f),
                                fmaxf(cf[(mt * 8 + nt) * 4 + 3], 0.f));
            }
        __syncwarp();
    }

    // =============== layer 2c: 64 -> 3, sigmoid (scalar fp32) ===============
    {
        float c0 = sm[OB2C + 0], c1 = sm[OB2C + 1], c2 = sm[OB2C + 2];
        int zr = actB + ln * ACT_STRIDE;
        #pragma unroll 8
        for (int k = 0; k < 64; k++) {
            float v = sm[zr + k];
            c0 = fmaf(v, sm[OW2C + 3 * k + 0], c0);
            c1 = fmaf(v, sm[OW2C + 3 * k + 1], c1);
            c2 = fmaf(v, sm[OW2C + 3 * k + 2], c2);
        }
        c0 = 1.0f / (1.0f + __expf(-c0));
        c1 = 1.0f / (1.0f + __expf(-c1));
        c2 = 1.0f / (1.0f + __expf(-c2));

        if (valid) {
            out[3 * pt + 0] = mask ? c0 : 0.0f;
            out[3 * pt + 1] = mask ? c1 : 0.0f;
            out[3 * pt + 2] = mask ? c2 : 0.0f;
            out[3 * n + pt] = sigma;
        }
    }
}

extern "C" void kernel_launch(void* const* d_in, const int* in_sizes, int n_in,
                              void* d_out, int out_size) {
    const float* x      = (const float*)d_in[0];
    const float* dd     = (const float*)d_in[1];
    const float* tables = (const float*)d_in[2];

    int n = in_sizes[0] / 3;

    int t1 = 256;
    ngp_gather_kernel<<<(n + t1 - 1) / t1, t1>>>(x, tables, n);

    cudaFuncSetAttribute(ngp_mlp_kernel,
                         cudaFuncAttributeMaxDynamicSharedMemorySize, SMEM_BYTES);
    int blocks = (n + 127) / 128;
    ngp_mlp_kernel<<<blocks, 128, SMEM_BYTES>>>(
        x, dd,
        (const float*)d_in[3], (const float*)d_in[4],
        (const float*)d_in[5], (const float*)d_in[6],
        (const float*)d_in[7], (const float*)d_in[8],
        (const float*)d_in[9], (const float*)d_in[10],
        (const float*)d_in[11], (const float*)d_in[12],
        (float*)d_out, n);
}